// round 8
// baseline (speedup 1.0000x reference)
#include <cuda_runtime.h>
#include <cstdint>

#define BB   32
#define TT   336
#define NH   100
#define NM   150
#define FH   8
#define FM   16
#define HG   64
#define HL   64
#define FUT  24
#define TB   16   // graphs per gnn block

typedef unsigned long long u64;

// Packed fp32 FMA (per-lane .rn, bitwise == scalar FFMA)
#define FMA2(d, a, b) \
    asm("fma.rn.f32x2 %0, %1, %2, %0;" : "+l"(d) : "l"(a), "l"(b))
#define PACK2(d, v) \
    asm("mov.b64 %0, {%1, %1};" : "=l"(d) : "r"(__float_as_uint(v)))
#define UNPACK2(lo, hi, x) \
    asm("mov.b64 {%0, %1}, %2;" : "=f"(lo), "=f"(hi) : "l"(x))

// GNN output x: [n][t][b][hg]
__device__ float g_x[(size_t)NH * TT * BB * HG];

// CSR edge structure (built once per launch, deterministic order)
__device__ int d_off_h[NH], d_deg_h[NH], d_src_h[512];
__device__ int d_off_m[NH], d_deg_m[NH], d_src_m[1024];

// ---------------------------------------------------------------------------
// Kernel A0: build CSR by target node (deterministic, one block).
// ---------------------------------------------------------------------------
__global__ void __launch_bounds__(256) csr_kernel(
    const int* __restrict__ eh, const int* __restrict__ em, int Eh, int Em)
{
    __shared__ int s_src[1024], s_tgt[1024];
    const int tid = threadIdx.x;

    for (int i = tid; i < Eh; i += 256) { s_src[i] = eh[i]; s_tgt[i] = eh[Eh + i]; }
    __syncthreads();
    if (tid < NH) {
        int start = 0;
        for (int e = 0; e < Eh; e++) start += (s_tgt[e] < tid) ? 1 : 0;
        int p = start, cnt = 0;
        for (int e = 0; e < Eh; e++)
            if (s_tgt[e] == tid) { d_src_h[p++] = s_src[e]; cnt++; }
        d_off_h[tid] = start; d_deg_h[tid] = cnt;
    }
    __syncthreads();
    for (int i = tid; i < Em; i += 256) { s_src[i] = em[i]; s_tgt[i] = em[Em + i]; }
    __syncthreads();
    if (tid < NH) {
        int start = 0;
        for (int e = 0; e < Em; e++) start += (s_tgt[e] < tid) ? 1 : 0;
        int p = start, cnt = 0;
        for (int e = 0; e < Em; e++)
            if (s_tgt[e] == tid) { d_src_m[p++] = s_src[e]; cnt++; }
        d_off_m[tid] = start; d_deg_m[tid] = cnt;
    }
}

// ---------------------------------------------------------------------------
// Kernel A: hetero GraphConv, TB graphs per block, CSR gather. (R6, verified)
// ---------------------------------------------------------------------------
__global__ void __launch_bounds__(256) gnn_kernel(
    const float* __restrict__ xm_all, const float* __restrict__ xh_all,
    const float* __restrict__ Wrel_m, const float* __restrict__ brel_m,
    const float* __restrict__ Wroot_m,
    const float* __restrict__ Wrel_h, const float* __restrict__ brel_h,
    const float* __restrict__ Wroot_h)
{
    __shared__ float swh[FH * HG];
    __shared__ float swr[FH * HG];
    __shared__ float swm[FM * HG];
    __shared__ float sb[HG];
    __shared__ int soff_h[NH], sdeg_h[NH], ssrc_h[512];
    __shared__ int soff_m[NH], sdeg_m[NH], ssrc_m[1024];
    __shared__ float sxh[NH * FH];
    __shared__ float sxm[NM * FM];
    __shared__ float sah[NH * FH];
    __shared__ float sam[NH * FM];

    const int tid = threadIdx.x;

    for (int i = tid; i < HG * FH; i += 256) {
        int j = i / FH, k = i % FH;
        swh[k * HG + j] = 0.5f * Wrel_h[i];
        swr[k * HG + j] = 0.5f * (Wroot_h[i] + Wroot_m[i]);
    }
    for (int i = tid; i < HG * FM; i += 256) {
        int j = i / FM, k = i % FM;
        swm[k * HG + j] = 0.5f * Wrel_m[i];
    }
    for (int i = tid; i < HG; i += 256) sb[i] = 0.5f * (brel_h[i] + brel_m[i]);
    for (int i = tid; i < NH; i += 256) {
        soff_h[i] = d_off_h[i]; sdeg_h[i] = d_deg_h[i];
        soff_m[i] = d_off_m[i]; sdeg_m[i] = d_deg_m[i];
    }
    for (int i = tid; i < 512;  i += 256) ssrc_h[i] = d_src_h[i];
    for (int i = tid; i < 1024; i += 256) ssrc_m[i] = d_src_m[i];

    for (int gi = 0; gi < TB; gi++) {
        const int g = blockIdx.x * TB + gi;
        const float* xh = xh_all + (size_t)g * NH * FH;
        const float* xm = xm_all + (size_t)g * NM * FM;

        __syncthreads();
        for (int i = tid; i < NH * FH / 4; i += 256)
            *(float4*)&sxh[i * 4] = *(const float4*)&xh[i * 4];
        for (int i = tid; i < NM * FM / 4; i += 256)
            *(float4*)&sxm[i * 4] = *(const float4*)&xm[i * 4];
        __syncthreads();

        for (int idx = tid; idx < NH * FH; idx += 256) {
            int n = idx >> 3, k = idx & 7;
            int o = soff_h[n], d = sdeg_h[n];
            float s = 0.f;
            for (int e = 0; e < d; e++) s += sxh[ssrc_h[o + e] * FH + k];
            sah[idx] = s;
        }
        for (int idx = tid; idx < NH * FM; idx += 256) {
            int n = idx >> 4, k = idx & 15;
            int o = soff_m[n], d = sdeg_m[n];
            float s = 0.f;
            for (int e = 0; e < d; e++) s += sxm[ssrc_m[o + e] * FM + k];
            sam[idx] = s;
        }
        __syncthreads();

        const int t = g % TT;
        const int b = g / TT;
        for (int idx = tid; idx < NH * HG; idx += 256) {
            int n = idx >> 6, j = idx & 63;
            float acc = sb[j];
            #pragma unroll
            for (int k = 0; k < FH; k++)
                acc += sah[n * FH + k] * swh[k * HG + j]
                     + sxh[n * FH + k] * swr[k * HG + j];
            #pragma unroll
            for (int k = 0; k < FM; k++)
                acc += sam[n * FM + k] * swm[k * HG + j];
            float v = acc > 0.f ? acc : 0.01f * acc;
            g_x[(((size_t)n * TT + t) * BB + b) * HG + j] = v;
        }
    }
}

// ---------------------------------------------------------------------------
// Kernel C: FUSED recurrent LSTM. One block per node, 512 threads.
// Both W_ih and W_hh resident in SMEM; each step's k-loop simultaneously
//   - accumulates h(t)@W_hh into acc (completing gates(t)), and
//   - accumulates x(t+1)@W_ih into gb (next step's x-gates).
// Thread mapping: b = tid&31 (batch lane), ug = tid>>5 (0..15) -> units
// ug*4..ug*4+3, all 4 gates. Weight reads are warp-broadcast LDS.128.
// ---------------------------------------------------------------------------
#define L_SWH  0                      // repacked W_hh: 16384
#define L_SWI  16384                  // repacked W_ih: 16384
#define L_SB   32768                  // repacked bias: 256
#define L_SH   (32768 + 256)          // 2 x [k*32 + b]: 4096
#define L_SX   (L_SH + 4096)          // 2 x [k][b] stride 33: 2*2112
#define L_WL   (L_SX + 2*2112)        // 24*64
#define L_BL   (L_WL + 24*64)
#define LS_FLOATS (L_BL + 32)
#define LS_BYTES  (LS_FLOATS * 4)

__device__ __forceinline__ float sigm(float x) {
    return 1.0f / (1.0f + __expf(-x));
}
__device__ __forceinline__ float tanh_fast(float x) {
    float xc = fminf(fmaxf(x, -15.f), 15.f);
    float e = __expf(2.0f * xc);
    return (e - 1.0f) / (e + 1.0f);
}

__global__ void __launch_bounds__(512) lstm_kernel(
    const float* __restrict__ W_ih, const float* __restrict__ W_hh,
    const float* __restrict__ b_ih, const float* __restrict__ b_hh,
    const float* __restrict__ W_lin, const float* __restrict__ b_lin,
    float* __restrict__ out)
{
    extern __shared__ float sm[];
    float* sWh   = sm + L_SWH;   // [k][ug*16 + gg*4 + uu]
    float* sWi   = sm + L_SWI;   // same layout
    float* sb2   = sm + L_SB;    // [ug*16 + gg*4 + uu]
    float* sh    = sm + L_SH;    // 2 x [k*32 + b]
    float* sx    = sm + L_SX;    // 2 x [k*33 + b]
    float* sWlin = sm + L_WL;
    float* sblin = sm + L_BL;

    const int n   = blockIdx.x;
    const int tid = threadIdx.x;
    const int b   = tid & 31;
    const int ug  = tid >> 5;    // 0..15

    // repack both weight matrices: src[j*64+k], j = gg*64 + ug*4 + uu
    const float* wih = W_ih + (size_t)n * 16384;
    const float* whh = W_hh + (size_t)n * 16384;
    for (int i = tid; i < 16384; i += 512) {
        int j = i >> 6, k = i & 63;
        int gg = j >> 6, r = j & 63, ugx = r >> 2, uu = r & 3;
        int dst = k * 256 + ugx * 16 + gg * 4 + uu;
        sWh[dst] = whh[i];
        sWi[dst] = wih[i];
    }
    if (tid < 256) {
        int j = tid;
        int gg = j >> 6, r = j & 63, ugx = r >> 2, uu = r & 3;
        sb2[ugx * 16 + gg * 4 + uu] = b_ih[n * 256 + j] + b_hh[n * 256 + j];
    }
    for (int i = tid; i < FUT * HL; i += 512) sWlin[i] = W_lin[i];
    if (tid < FUT) sblin[tid] = b_lin[tid];
    for (int i = tid; i < 2048; i += 512) sh[i] = 0.f;   // h0 (buffer 0)

    // x staging map: thread loads x[b_s][k4..k4+3] (coalesced float4)
    const int b_s = tid >> 4;          // 0..31
    const int k4  = (tid & 15) * 4;    // 0..60

    const float* xsrc = g_x + (size_t)n * TT * BB * HG;

    // stage x(0) into sx buffer 0
    {
        float4 v = *(const float4*)&xsrc[(size_t)b_s * HG + k4];
        float* sxd = sx;   // buffer 0
        sxd[(k4 + 0) * 33 + b_s] = v.x;
        sxd[(k4 + 1) * 33 + b_s] = v.y;
        sxd[(k4 + 2) * 33 + b_s] = v.z;
        sxd[(k4 + 3) * 33 + b_s] = v.w;
    }
    __syncthreads();

    // bias registers (packed)
    u64 bias8[8];
    #pragma unroll
    for (int q = 0; q < 4; q++) {
        float4 bv = *(const float4*)&sb2[ug * 16 + 4 * q];
        bias8[2 * q + 0] = *(const u64*)&bv.x;
        bias8[2 * q + 1] = *(const u64*)&bv.z;
    }

    // pre-loop: gb(0) = bias + x(0)@W_ih
    u64 gb[8];
    #pragma unroll
    for (int q = 0; q < 8; q++) gb[q] = bias8[q];
    {
        const float* sxb = sx;   // buffer 0
        #pragma unroll 4
        for (int k = 0; k < 64; k++) {
            u64 xx;
            PACK2(xx, sxb[k * 33 + b]);
            const float* wi = &sWi[k * 256 + ug * 16];
            #pragma unroll
            for (int gg = 0; gg < 4; gg++) {
                float4 wv = *(const float4*)&wi[gg * 4];
                FMA2(gb[gg * 2 + 0], xx, *(const u64*)&wv.x);
                FMA2(gb[gg * 2 + 1], xx, *(const u64*)&wv.z);
            }
        }
    }

    float c[4];
    #pragma unroll
    for (int q = 0; q < 4; q++) c[q] = 0.f;

    for (int t = 0; t < TT; t++) {
        // stage x(t+1) into sx[(t+1)&1] (pre-barrier; parity-safe)
        if (t + 1 < TT) {
            float4 v = *(const float4*)
                &xsrc[((size_t)(t + 1) * BB + b_s) * HG + k4];
            float* sxd = sx + ((t + 1) & 1) * 2112;
            sxd[(k4 + 0) * 33 + b_s] = v.x;
            sxd[(k4 + 1) * 33 + b_s] = v.y;
            sxd[(k4 + 2) * 33 + b_s] = v.z;
            sxd[(k4 + 3) * 33 + b_s] = v.w;
        }

        // move gates(t) into acc; reset gb to bias for gates(t+1)
        u64 acc[8];
        #pragma unroll
        for (int q = 0; q < 8; q++) { acc[q] = gb[q]; gb[q] = bias8[q]; }

        const float* hb  = sh + (t & 1) * 2048;
        float*       hw  = sh + ((t + 1) & 1) * 2048;
        const float* sxb = sx + ((t + 1) & 1) * 2112;
        __syncthreads();   // h(t) + x(t+1) staged visible

        #pragma unroll 4
        for (int k = 0; k < 64; k++) {
            u64 hx, xx;
            PACK2(hx, hb[k * 32 + b]);
            PACK2(xx, sxb[k * 33 + b]);
            const float* wh = &sWh[k * 256 + ug * 16];
            const float* wi = &sWi[k * 256 + ug * 16];
            #pragma unroll
            for (int gg = 0; gg < 4; gg++) {
                float4 wv = *(const float4*)&wh[gg * 4];
                FMA2(acc[gg * 2 + 0], hx, *(const u64*)&wv.x);
                FMA2(acc[gg * 2 + 1], hx, *(const u64*)&wv.z);
            }
            #pragma unroll
            for (int gg = 0; gg < 4; gg++) {
                float4 wv = *(const float4*)&wi[gg * 4];
                FMA2(gb[gg * 2 + 0], xx, *(const u64*)&wv.x);
                FMA2(gb[gg * 2 + 1], xx, *(const u64*)&wv.z);
            }
        }

        // cell update (gate order i, f, g, o); 4 units per thread
        #pragma unroll
        for (int p = 0; p < 2; p++) {
            float iv[2], fv[2], gv[2], ov[2];
            UNPACK2(iv[0], iv[1], acc[0 * 2 + p]);
            UNPACK2(fv[0], fv[1], acc[1 * 2 + p]);
            UNPACK2(gv[0], gv[1], acc[2 * 2 + p]);
            UNPACK2(ov[0], ov[1], acc[3 * 2 + p]);
            #pragma unroll
            for (int du = 0; du < 2; du++) {
                int q = 2 * p + du;
                float ig = sigm(iv[du]);
                float fg = sigm(fv[du]);
                float gg = tanh_fast(gv[du]);
                float og = sigm(ov[du]);
                float cc = fg * c[q] + ig * gg;
                c[q] = cc;
                hw[(ug * 4 + q) * 32 + b] = og * tanh_fast(cc);
            }
        }
    }
    __syncthreads();

    // h_last in buffer 0 (TT even): sh[u*32 + b]
    for (int idx = tid; idx < BB * FUT; idx += 512) {
        int bb = idx / FUT;
        int f  = idx % FUT;
        float acc = sblin[f];
        #pragma unroll
        for (int u = 0; u < HL; u++)
            acc += sh[u * 32 + bb] * sWlin[f * HL + u];
        float v = acc > 0.f ? acc : 0.01f * acc;
        out[((size_t)bb * NH + n) * FUT + f] = v;
    }
}

// ---------------------------------------------------------------------------
extern "C" void kernel_launch(void* const* d_in, const int* in_sizes, int n_in,
                              void* d_out, int out_size)
{
    const float* data_meteo = (const float*)d_in[0];
    const float* data_hydro = (const float*)d_in[1];
    const int*   eh         = (const int*)  d_in[2];
    const int*   em         = (const int*)  d_in[3];
    const float* W_rel_m    = (const float*)d_in[4];
    const float* b_rel_m    = (const float*)d_in[5];
    const float* W_root_m   = (const float*)d_in[6];
    const float* W_rel_h    = (const float*)d_in[7];
    const float* b_rel_h    = (const float*)d_in[8];
    const float* W_root_h   = (const float*)d_in[9];
    const float* W_ih       = (const float*)d_in[10];
    const float* W_hh       = (const float*)d_in[11];
    const float* b_ih       = (const float*)d_in[12];
    const float* b_hh       = (const float*)d_in[13];
    const float* W_lin      = (const float*)d_in[14];
    const float* b_lin      = (const float*)d_in[15];

    const int Eh = in_sizes[2] / 2;
    const int Em = in_sizes[3] / 2;

    csr_kernel<<<1, 256>>>(eh, em, Eh, Em);

    gnn_kernel<<<(BB * TT) / TB, 256>>>(data_meteo, data_hydro,
                                        W_rel_m, b_rel_m, W_root_m,
                                        W_rel_h, b_rel_h, W_root_h);

    cudaFuncSetAttribute(lstm_kernel,
                         cudaFuncAttributeMaxDynamicSharedMemorySize, LS_BYTES);
    lstm_kernel<<<NH, 512, LS_BYTES>>>(W_ih, W_hh, b_ih, b_hh,
                                       W_lin, b_lin, (float*)d_out);
}

// round 9
// speedup vs baseline: 1.1410x; 1.1410x over previous
#include <cuda_runtime.h>
#include <cstdint>

#define BB   32
#define TT   336
#define NH   100
#define NM   150
#define FH   8
#define FM   16
#define HG   64
#define HL   64
#define FUT  24
#define TC   16   // timesteps per precompute block
#define TB   16   // graphs per gnn block
#define QB   8    // batches per lstm block
#define NQ   (BB / QB)   // lstm blocks per node = 4

// GNN output x: [n][t][b][hg]
__device__ float g_x[(size_t)NH * TT * BB * HG];
// Precomputed x-gates (+bias): [n][t][b][256]
__device__ float g_gates[(size_t)NH * TT * BB * 256];

// CSR edge structure (built once per launch, deterministic order)
__device__ int d_off_h[NH], d_deg_h[NH], d_src_h[512];
__device__ int d_off_m[NH], d_deg_m[NH], d_src_m[1024];

// ---------------------------------------------------------------------------
// Kernel A0: build CSR by target node (deterministic, one block).
// ---------------------------------------------------------------------------
__global__ void __launch_bounds__(256) csr_kernel(
    const int* __restrict__ eh, const int* __restrict__ em, int Eh, int Em)
{
    __shared__ int s_src[1024], s_tgt[1024];
    const int tid = threadIdx.x;

    for (int i = tid; i < Eh; i += 256) { s_src[i] = eh[i]; s_tgt[i] = eh[Eh + i]; }
    __syncthreads();
    if (tid < NH) {
        int start = 0;
        for (int e = 0; e < Eh; e++) start += (s_tgt[e] < tid) ? 1 : 0;
        int p = start, cnt = 0;
        for (int e = 0; e < Eh; e++)
            if (s_tgt[e] == tid) { d_src_h[p++] = s_src[e]; cnt++; }
        d_off_h[tid] = start; d_deg_h[tid] = cnt;
    }
    __syncthreads();
    for (int i = tid; i < Em; i += 256) { s_src[i] = em[i]; s_tgt[i] = em[Em + i]; }
    __syncthreads();
    if (tid < NH) {
        int start = 0;
        for (int e = 0; e < Em; e++) start += (s_tgt[e] < tid) ? 1 : 0;
        int p = start, cnt = 0;
        for (int e = 0; e < Em; e++)
            if (s_tgt[e] == tid) { d_src_m[p++] = s_src[e]; cnt++; }
        d_off_m[tid] = start; d_deg_m[tid] = cnt;
    }
}

// ---------------------------------------------------------------------------
// Kernel A: hetero GraphConv, TB graphs per block, CSR gather. (R6, verified)
// ---------------------------------------------------------------------------
__global__ void __launch_bounds__(256) gnn_kernel(
    const float* __restrict__ xm_all, const float* __restrict__ xh_all,
    const float* __restrict__ Wrel_m, const float* __restrict__ brel_m,
    const float* __restrict__ Wroot_m,
    const float* __restrict__ Wrel_h, const float* __restrict__ brel_h,
    const float* __restrict__ Wroot_h)
{
    __shared__ float swh[FH * HG];
    __shared__ float swr[FH * HG];
    __shared__ float swm[FM * HG];
    __shared__ float sb[HG];
    __shared__ int soff_h[NH], sdeg_h[NH], ssrc_h[512];
    __shared__ int soff_m[NH], sdeg_m[NH], ssrc_m[1024];
    __shared__ float sxh[NH * FH];
    __shared__ float sxm[NM * FM];
    __shared__ float sah[NH * FH];
    __shared__ float sam[NH * FM];

    const int tid = threadIdx.x;

    for (int i = tid; i < HG * FH; i += 256) {
        int j = i / FH, k = i % FH;
        swh[k * HG + j] = 0.5f * Wrel_h[i];
        swr[k * HG + j] = 0.5f * (Wroot_h[i] + Wroot_m[i]);
    }
    for (int i = tid; i < HG * FM; i += 256) {
        int j = i / FM, k = i % FM;
        swm[k * HG + j] = 0.5f * Wrel_m[i];
    }
    for (int i = tid; i < HG; i += 256) sb[i] = 0.5f * (brel_h[i] + brel_m[i]);
    for (int i = tid; i < NH; i += 256) {
        soff_h[i] = d_off_h[i]; sdeg_h[i] = d_deg_h[i];
        soff_m[i] = d_off_m[i]; sdeg_m[i] = d_deg_m[i];
    }
    for (int i = tid; i < 512;  i += 256) ssrc_h[i] = d_src_h[i];
    for (int i = tid; i < 1024; i += 256) ssrc_m[i] = d_src_m[i];

    for (int gi = 0; gi < TB; gi++) {
        const int g = blockIdx.x * TB + gi;
        const float* xh = xh_all + (size_t)g * NH * FH;
        const float* xm = xm_all + (size_t)g * NM * FM;

        __syncthreads();
        for (int i = tid; i < NH * FH / 4; i += 256)
            *(float4*)&sxh[i * 4] = *(const float4*)&xh[i * 4];
        for (int i = tid; i < NM * FM / 4; i += 256)
            *(float4*)&sxm[i * 4] = *(const float4*)&xm[i * 4];
        __syncthreads();

        for (int idx = tid; idx < NH * FH; idx += 256) {
            int n = idx >> 3, k = idx & 7;
            int o = soff_h[n], d = sdeg_h[n];
            float s = 0.f;
            for (int e = 0; e < d; e++) s += sxh[ssrc_h[o + e] * FH + k];
            sah[idx] = s;
        }
        for (int idx = tid; idx < NH * FM; idx += 256) {
            int n = idx >> 4, k = idx & 15;
            int o = soff_m[n], d = sdeg_m[n];
            float s = 0.f;
            for (int e = 0; e < d; e++) s += sxm[ssrc_m[o + e] * FM + k];
            sam[idx] = s;
        }
        __syncthreads();

        const int t = g % TT;
        const int b = g / TT;
        for (int idx = tid; idx < NH * HG; idx += 256) {
            int n = idx >> 6, j = idx & 63;
            float acc = sb[j];
            #pragma unroll
            for (int k = 0; k < FH; k++)
                acc += sah[n * FH + k] * swh[k * HG + j]
                     + sxh[n * FH + k] * swr[k * HG + j];
            #pragma unroll
            for (int k = 0; k < FM; k++)
                acc += sam[n * FM + k] * swm[k * HG + j];
            float v = acc > 0.f ? acc : 0.01f * acc;
            g_x[(((size_t)n * TT + t) * BB + b) * HG + j] = v;
        }
    }
}

// ---------------------------------------------------------------------------
// Kernel B: x-gate precompute. grid (NH, TT/TC), 256 threads, 3 blocks/SM.
// (exact Round-2/6 version, verified)
// ---------------------------------------------------------------------------
#define XG_SW 0                 // [k][j] stride 256  (16384 floats)
#define XG_SB 16384             // 256
#define XG_SX (16384 + 256)     // [k][b] stride 33
#define XG_FLOATS (XG_SX + 64*33)
#define XG_BYTES  (XG_FLOATS * 4)

__global__ void __launch_bounds__(256, 3) xgemm_kernel(
    const float* __restrict__ W_ih,
    const float* __restrict__ b_ih, const float* __restrict__ b_hh)
{
    extern __shared__ float sm[];
    float* sW = sm + XG_SW;
    float* sb = sm + XG_SB;
    float* sx = sm + XG_SX;

    const int n   = blockIdx.x;
    const int t0  = blockIdx.y * TC;
    const int tid = threadIdx.x;

    const float* w = W_ih + (size_t)n * 256 * 64;
    for (int i = tid; i < 16384; i += 256) {
        int j = i >> 6, k = i & 63;
        sW[k * 256 + j] = w[i];
    }
    sb[tid] = b_ih[n * 256 + tid] + b_hh[n * 256 + tid];

    const int tm = tid >> 5;
    const int tn = tid & 31;
    const int sb_b = tid >> 3;
    const int sb_k = (tid & 7) << 3;

    const float* xbase = g_x + ((size_t)n * TT + t0) * BB * HG;
    float* gbase = g_gates + ((size_t)n * TT + t0) * BB * 256;
    __syncthreads();

    for (int tt = 0; tt < TC; tt++) {
        const float* xt = xbase + (size_t)tt * BB * HG;
        float4 v0 = *(const float4*)&xt[sb_b * HG + sb_k];
        float4 v1 = *(const float4*)&xt[sb_b * HG + sb_k + 4];
        sx[(sb_k + 0) * 33 + sb_b] = v0.x;
        sx[(sb_k + 1) * 33 + sb_b] = v0.y;
        sx[(sb_k + 2) * 33 + sb_b] = v0.z;
        sx[(sb_k + 3) * 33 + sb_b] = v0.w;
        sx[(sb_k + 4) * 33 + sb_b] = v1.x;
        sx[(sb_k + 5) * 33 + sb_b] = v1.y;
        sx[(sb_k + 6) * 33 + sb_b] = v1.z;
        sx[(sb_k + 7) * 33 + sb_b] = v1.w;
        __syncthreads();

        float acc[4][8];
        #pragma unroll
        for (int mi = 0; mi < 4; mi++)
            #pragma unroll
            for (int gg = 0; gg < 4; gg++) {
                acc[mi][gg * 2 + 0] = sb[gg * 64 + 2 * tn + 0];
                acc[mi][gg * 2 + 1] = sb[gg * 64 + 2 * tn + 1];
            }

        #pragma unroll 4
        for (int k = 0; k < 64; k++) {
            float xv[4];
            #pragma unroll
            for (int mi = 0; mi < 4; mi++) xv[mi] = sx[k * 33 + 4 * tm + mi];
            #pragma unroll
            for (int gg = 0; gg < 4; gg++) {
                float2 wv = *(const float2*)&sW[k * 256 + gg * 64 + 2 * tn];
                #pragma unroll
                for (int mi = 0; mi < 4; mi++) {
                    acc[mi][gg * 2 + 0] += xv[mi] * wv.x;
                    acc[mi][gg * 2 + 1] += xv[mi] * wv.y;
                }
            }
        }

        float* gt = gbase + (size_t)tt * BB * 256;
        #pragma unroll
        for (int mi = 0; mi < 4; mi++)
            #pragma unroll
            for (int gg = 0; gg < 4; gg++) {
                float2 v; v.x = acc[mi][gg * 2]; v.y = acc[mi][gg * 2 + 1];
                *(float2*)&gt[(4 * tm + mi) * 256 + gg * 64 + 2 * tn] = v;
            }
        __syncthreads();
    }
}

// ---------------------------------------------------------------------------
// Kernel C: recurrent LSTM, BATCH-SPLIT: grid NH*NQ, 256 threads.
// Block (n, q) handles batches q*8..q*8+7 of node n (batches are independent
// LSTM sequences). Warp = one batch (tm), tn = unit pair {2tn, 2tn+1}.
// W_hh resident in SMEM per block (duplicated across the node's 4 blocks).
// ---------------------------------------------------------------------------
#define O_WHH 0
#define O_H   16384               // 2 x [k][b] stride 9 (576 each)
#define HBUF  (64*9)
#define LS_FLOATS (O_H + 2*HBUF + 32)
#define LS_BYTES  (LS_FLOATS * 4)

__device__ __forceinline__ float sigm(float x) {
    return 1.0f / (1.0f + __expf(-x));
}
__device__ __forceinline__ float tanh_fast(float x) {
    float xc = fminf(fmaxf(x, -15.f), 15.f);
    float e = __expf(2.0f * xc);
    return (e - 1.0f) / (e + 1.0f);
}

__global__ void __launch_bounds__(256) lstm_kernel(
    const float* __restrict__ W_hh,
    const float* __restrict__ W_lin, const float* __restrict__ b_lin,
    float* __restrict__ out)
{
    extern __shared__ float sm[];
    float* sWhh = sm + O_WHH;   // [k][j] stride 256
    float* sh   = sm + O_H;     // 2 x [k][b] stride 9

    const int n   = blockIdx.x / NQ;
    const int b0  = (blockIdx.x % NQ) * QB;
    const int tid = threadIdx.x;
    const int tm  = tid >> 5;   // warp id = local batch 0..7
    const int tn  = tid & 31;   // unit pair

    const float* whh = W_hh + (size_t)n * 256 * 64;
    for (int i = tid; i < 16384; i += 256) {
        int j = i >> 6, k = i & 63;
        sWhh[k * 256 + j] = whh[i];
    }
    for (int i = tid; i < HBUF; i += 256) sh[i] = 0.f;   // h0 buffer

    float c0 = 0.f, c1 = 0.f;

    // gates for this block's batches: [t][b0+tm][256]
    const float* gptr = g_gates + ((size_t)n * TT * BB + b0) * 256;

    // prefetch gates(t=0)
    float gb[8];
    #pragma unroll
    for (int gg = 0; gg < 4; gg++) {
        float2 v = *(const float2*)&gptr[tm * 256 + gg * 64 + 2 * tn];
        gb[gg * 2] = v.x; gb[gg * 2 + 1] = v.y;
    }

    for (int t = 0; t < TT; t++) {
        float acc[8];
        #pragma unroll
        for (int q = 0; q < 8; q++) acc[q] = gb[q];

        // prefetch gates(t+1) — latency hidden under k-loop
        if (t + 1 < TT) {
            const float* gnx = gptr + (size_t)(t + 1) * BB * 256;
            #pragma unroll
            for (int gg = 0; gg < 4; gg++) {
                float2 v = *(const float2*)&gnx[tm * 256 + gg * 64 + 2 * tn];
                gb[gg * 2] = v.x; gb[gg * 2 + 1] = v.y;
            }
        }

        const float* hb = sh + (t & 1) * HBUF;
        float*       hw = sh + ((t + 1) & 1) * HBUF;
        __syncthreads();   // h(t) visible

        #pragma unroll 8
        for (int k = 0; k < 64; k++) {
            float hv = hb[k * 9 + tm];   // warp-broadcast
            #pragma unroll
            for (int gg = 0; gg < 4; gg++) {
                float2 w = *(const float2*)&sWhh[k * 256 + gg * 64 + 2 * tn];
                acc[gg * 2 + 0] += hv * w.x;
                acc[gg * 2 + 1] += hv * w.y;
            }
        }

        // cell update (gate order i, f, g, o); units 2tn, 2tn+1 of batch tm
        {
            float ig = sigm(acc[0]);
            float fg = sigm(acc[2]);
            float gv = tanh_fast(acc[4]);
            float og = sigm(acc[6]);
            float cc = fg * c0 + ig * gv;
            c0 = cc;
            hw[(2 * tn + 0) * 9 + tm] = og * tanh_fast(cc);
        }
        {
            float ig = sigm(acc[1]);
            float fg = sigm(acc[3]);
            float gv = tanh_fast(acc[5]);
            float og = sigm(acc[7]);
            float cc = fg * c1 + ig * gv;
            c1 = cc;
            hw[(2 * tn + 1) * 9 + tm] = og * tanh_fast(cc);
        }
    }
    __syncthreads();

    // h_last in buffer (TT & 1) == 0; head reads W_lin/b_lin straight from gmem
    const float* hl = sh;
    for (int idx = tid; idx < QB * FUT; idx += 256) {
        int bl = idx / FUT;
        int f  = idx % FUT;
        float acc = b_lin[f];
        #pragma unroll
        for (int u = 0; u < HL; u++)
            acc += hl[u * 9 + bl] * W_lin[f * HL + u];
        float v = acc > 0.f ? acc : 0.01f * acc;
        out[((size_t)(b0 + bl) * NH + n) * FUT + f] = v;
    }
}

// ---------------------------------------------------------------------------
extern "C" void kernel_launch(void* const* d_in, const int* in_sizes, int n_in,
                              void* d_out, int out_size)
{
    const float* data_meteo = (const float*)d_in[0];
    const float* data_hydro = (const float*)d_in[1];
    const int*   eh         = (const int*)  d_in[2];
    const int*   em         = (const int*)  d_in[3];
    const float* W_rel_m    = (const float*)d_in[4];
    const float* b_rel_m    = (const float*)d_in[5];
    const float* W_root_m   = (const float*)d_in[6];
    const float* W_rel_h    = (const float*)d_in[7];
    const float* b_rel_h    = (const float*)d_in[8];
    const float* W_root_h   = (const float*)d_in[9];
    const float* W_ih       = (const float*)d_in[10];
    const float* W_hh       = (const float*)d_in[11];
    const float* b_ih       = (const float*)d_in[12];
    const float* b_hh       = (const float*)d_in[13];
    const float* W_lin      = (const float*)d_in[14];
    const float* b_lin      = (const float*)d_in[15];

    const int Eh = in_sizes[2] / 2;
    const int Em = in_sizes[3] / 2;

    csr_kernel<<<1, 256>>>(eh, em, Eh, Em);

    gnn_kernel<<<(BB * TT) / TB, 256>>>(data_meteo, data_hydro,
                                        W_rel_m, b_rel_m, W_root_m,
                                        W_rel_h, b_rel_h, W_root_h);

    cudaFuncSetAttribute(xgemm_kernel,
                         cudaFuncAttributeMaxDynamicSharedMemorySize, XG_BYTES);
    dim3 xg(NH, TT / TC);
    xgemm_kernel<<<xg, 256, XG_BYTES>>>(W_ih, b_ih, b_hh);

    cudaFuncSetAttribute(lstm_kernel,
                         cudaFuncAttributeMaxDynamicSharedMemorySize, LS_BYTES);
    lstm_kernel<<<NH * NQ, 256, LS_BYTES>>>(W_hh, W_lin, b_lin, (float*)d_out);
}

// round 10
// speedup vs baseline: 1.2643x; 1.1080x over previous
#include <cuda_runtime.h>
#include <cstdint>

#define BB   32
#define TT   336
#define NH   100
#define NM   150
#define FH   8
#define FM   16
#define HG   64
#define HL   64
#define FUT  24
#define TC   16   // timesteps per precompute block
#define TB   16   // graphs per gnn block

// GNN output x: [n][t][b][hg]
__device__ float g_x[(size_t)NH * TT * BB * HG];
// Precomputed x-gates (+bias): [n][t][b][256]
__device__ float g_gates[(size_t)NH * TT * BB * 256];

// CSR edge structure (built once per launch, deterministic order)
__device__ int d_off_h[NH], d_deg_h[NH], d_src_h[512];
__device__ int d_off_m[NH], d_deg_m[NH], d_src_m[1024];

// ---------------------------------------------------------------------------
// Kernel A0: build CSR by target node (deterministic, one block).
// ---------------------------------------------------------------------------
__global__ void __launch_bounds__(256) csr_kernel(
    const int* __restrict__ eh, const int* __restrict__ em, int Eh, int Em)
{
    __shared__ int s_src[1024], s_tgt[1024];
    const int tid = threadIdx.x;

    for (int i = tid; i < Eh; i += 256) { s_src[i] = eh[i]; s_tgt[i] = eh[Eh + i]; }
    __syncthreads();
    if (tid < NH) {
        int start = 0;
        for (int e = 0; e < Eh; e++) start += (s_tgt[e] < tid) ? 1 : 0;
        int p = start, cnt = 0;
        for (int e = 0; e < Eh; e++)
            if (s_tgt[e] == tid) { d_src_h[p++] = s_src[e]; cnt++; }
        d_off_h[tid] = start; d_deg_h[tid] = cnt;
    }
    __syncthreads();
    for (int i = tid; i < Em; i += 256) { s_src[i] = em[i]; s_tgt[i] = em[Em + i]; }
    __syncthreads();
    if (tid < NH) {
        int start = 0;
        for (int e = 0; e < Em; e++) start += (s_tgt[e] < tid) ? 1 : 0;
        int p = start, cnt = 0;
        for (int e = 0; e < Em; e++)
            if (s_tgt[e] == tid) { d_src_m[p++] = s_src[e]; cnt++; }
        d_off_m[tid] = start; d_deg_m[tid] = cnt;
    }
}

// ---------------------------------------------------------------------------
// Kernel A: hetero GraphConv, TB graphs per block, CSR gather. (R6, verified)
// ---------------------------------------------------------------------------
__global__ void __launch_bounds__(256) gnn_kernel(
    const float* __restrict__ xm_all, const float* __restrict__ xh_all,
    const float* __restrict__ Wrel_m, const float* __restrict__ brel_m,
    const float* __restrict__ Wroot_m,
    const float* __restrict__ Wrel_h, const float* __restrict__ brel_h,
    const float* __restrict__ Wroot_h)
{
    __shared__ float swh[FH * HG];
    __shared__ float swr[FH * HG];
    __shared__ float swm[FM * HG];
    __shared__ float sb[HG];
    __shared__ int soff_h[NH], sdeg_h[NH], ssrc_h[512];
    __shared__ int soff_m[NH], sdeg_m[NH], ssrc_m[1024];
    __shared__ float sxh[NH * FH];
    __shared__ float sxm[NM * FM];
    __shared__ float sah[NH * FH];
    __shared__ float sam[NH * FM];

    const int tid = threadIdx.x;

    for (int i = tid; i < HG * FH; i += 256) {
        int j = i / FH, k = i % FH;
        swh[k * HG + j] = 0.5f * Wrel_h[i];
        swr[k * HG + j] = 0.5f * (Wroot_h[i] + Wroot_m[i]);
    }
    for (int i = tid; i < HG * FM; i += 256) {
        int j = i / FM, k = i % FM;
        swm[k * HG + j] = 0.5f * Wrel_m[i];
    }
    for (int i = tid; i < HG; i += 256) sb[i] = 0.5f * (brel_h[i] + brel_m[i]);
    for (int i = tid; i < NH; i += 256) {
        soff_h[i] = d_off_h[i]; sdeg_h[i] = d_deg_h[i];
        soff_m[i] = d_off_m[i]; sdeg_m[i] = d_deg_m[i];
    }
    for (int i = tid; i < 512;  i += 256) ssrc_h[i] = d_src_h[i];
    for (int i = tid; i < 1024; i += 256) ssrc_m[i] = d_src_m[i];

    for (int gi = 0; gi < TB; gi++) {
        const int g = blockIdx.x * TB + gi;
        const float* xh = xh_all + (size_t)g * NH * FH;
        const float* xm = xm_all + (size_t)g * NM * FM;

        __syncthreads();
        for (int i = tid; i < NH * FH / 4; i += 256)
            *(float4*)&sxh[i * 4] = *(const float4*)&xh[i * 4];
        for (int i = tid; i < NM * FM / 4; i += 256)
            *(float4*)&sxm[i * 4] = *(const float4*)&xm[i * 4];
        __syncthreads();

        for (int idx = tid; idx < NH * FH; idx += 256) {
            int n = idx >> 3, k = idx & 7;
            int o = soff_h[n], d = sdeg_h[n];
            float s = 0.f;
            for (int e = 0; e < d; e++) s += sxh[ssrc_h[o + e] * FH + k];
            sah[idx] = s;
        }
        for (int idx = tid; idx < NH * FM; idx += 256) {
            int n = idx >> 4, k = idx & 15;
            int o = soff_m[n], d = sdeg_m[n];
            float s = 0.f;
            for (int e = 0; e < d; e++) s += sxm[ssrc_m[o + e] * FM + k];
            sam[idx] = s;
        }
        __syncthreads();

        const int t = g % TT;
        const int b = g / TT;
        for (int idx = tid; idx < NH * HG; idx += 256) {
            int n = idx >> 6, j = idx & 63;
            float acc = sb[j];
            #pragma unroll
            for (int k = 0; k < FH; k++)
                acc += sah[n * FH + k] * swh[k * HG + j]
                     + sxh[n * FH + k] * swr[k * HG + j];
            #pragma unroll
            for (int k = 0; k < FM; k++)
                acc += sam[n * FM + k] * swm[k * HG + j];
            float v = acc > 0.f ? acc : 0.01f * acc;
            g_x[(((size_t)n * TT + t) * BB + b) * HG + j] = v;
        }
    }
}

// ---------------------------------------------------------------------------
// Kernel B: x-gate precompute. grid (NH, TT/TC), 256 threads, 3 blocks/SM.
// (exact Round-2/6 version, verified)
// ---------------------------------------------------------------------------
#define XG_SW 0                 // [k][j] stride 256  (16384 floats)
#define XG_SB 16384             // 256
#define XG_SX (16384 + 256)     // [k][b] stride 33
#define XG_FLOATS (XG_SX + 64*33)
#define XG_BYTES  (XG_FLOATS * 4)

__global__ void __launch_bounds__(256, 3) xgemm_kernel(
    const float* __restrict__ W_ih,
    const float* __restrict__ b_ih, const float* __restrict__ b_hh)
{
    extern __shared__ float sm[];
    float* sW = sm + XG_SW;
    float* sb = sm + XG_SB;
    float* sx = sm + XG_SX;

    const int n   = blockIdx.x;
    const int t0  = blockIdx.y * TC;
    const int tid = threadIdx.x;

    const float* w = W_ih + (size_t)n * 256 * 64;
    for (int i = tid; i < 16384; i += 256) {
        int j = i >> 6, k = i & 63;
        sW[k * 256 + j] = w[i];
    }
    sb[tid] = b_ih[n * 256 + tid] + b_hh[n * 256 + tid];

    const int tm = tid >> 5;
    const int tn = tid & 31;
    const int sb_b = tid >> 3;
    const int sb_k = (tid & 7) << 3;

    const float* xbase = g_x + ((size_t)n * TT + t0) * BB * HG;
    float* gbase = g_gates + ((size_t)n * TT + t0) * BB * 256;
    __syncthreads();

    for (int tt = 0; tt < TC; tt++) {
        const float* xt = xbase + (size_t)tt * BB * HG;
        float4 v0 = *(const float4*)&xt[sb_b * HG + sb_k];
        float4 v1 = *(const float4*)&xt[sb_b * HG + sb_k + 4];
        sx[(sb_k + 0) * 33 + sb_b] = v0.x;
        sx[(sb_k + 1) * 33 + sb_b] = v0.y;
        sx[(sb_k + 2) * 33 + sb_b] = v0.z;
        sx[(sb_k + 3) * 33 + sb_b] = v0.w;
        sx[(sb_k + 4) * 33 + sb_b] = v1.x;
        sx[(sb_k + 5) * 33 + sb_b] = v1.y;
        sx[(sb_k + 6) * 33 + sb_b] = v1.z;
        sx[(sb_k + 7) * 33 + sb_b] = v1.w;
        __syncthreads();

        float acc[4][8];
        #pragma unroll
        for (int mi = 0; mi < 4; mi++)
            #pragma unroll
            for (int gg = 0; gg < 4; gg++) {
                acc[mi][gg * 2 + 0] = sb[gg * 64 + 2 * tn + 0];
                acc[mi][gg * 2 + 1] = sb[gg * 64 + 2 * tn + 1];
            }

        #pragma unroll 4
        for (int k = 0; k < 64; k++) {
            float xv[4];
            #pragma unroll
            for (int mi = 0; mi < 4; mi++) xv[mi] = sx[k * 33 + 4 * tm + mi];
            #pragma unroll
            for (int gg = 0; gg < 4; gg++) {
                float2 wv = *(const float2*)&sW[k * 256 + gg * 64 + 2 * tn];
                #pragma unroll
                for (int mi = 0; mi < 4; mi++) {
                    acc[mi][gg * 2 + 0] += xv[mi] * wv.x;
                    acc[mi][gg * 2 + 1] += xv[mi] * wv.y;
                }
            }
        }

        float* gt = gbase + (size_t)tt * BB * 256;
        #pragma unroll
        for (int mi = 0; mi < 4; mi++)
            #pragma unroll
            for (int gg = 0; gg < 4; gg++) {
                float2 v; v.x = acc[mi][gg * 2]; v.y = acc[mi][gg * 2 + 1];
                *(float2*)&gt[(4 * tm + mi) * 256 + gg * 64 + 2 * tn] = v;
            }
        __syncthreads();
    }
}

// ---------------------------------------------------------------------------
// Kernel C: recurrent LSTM, WARP-LOCAL recurrence. One block per node,
// 256 threads = 8 independent warps; warp tm owns batches 4tm..4tm+3 and the
// full 64-unit recurrence for them. h lives in registers, distributed across
// lanes (lane l holds units {2l, 2l+1}); the GEMM reads h via __shfl_sync.
// ZERO barriers in the 336-step loop.
// ---------------------------------------------------------------------------
#define O_WHH 0
#define O_HL  16384               // h_last staging [u][b] stride 33: 2112
#define O_WL  (O_HL + 64*33)      // 24*64
#define O_BL  (O_WL + 24*64)
#define LS_FLOATS (O_BL + 32)
#define LS_BYTES  (LS_FLOATS * 4)

__device__ __forceinline__ float sigm(float x) {
    return 1.0f / (1.0f + __expf(-x));
}
__device__ __forceinline__ float tanh_fast(float x) {
    float xc = fminf(fmaxf(x, -15.f), 15.f);
    float e = __expf(2.0f * xc);
    return (e - 1.0f) / (e + 1.0f);
}

__global__ void __launch_bounds__(256) lstm_kernel(
    const float* __restrict__ W_hh,
    const float* __restrict__ W_lin, const float* __restrict__ b_lin,
    float* __restrict__ out)
{
    extern __shared__ float sm[];
    float* sWhh  = sm + O_WHH;   // [k][j] stride 256
    float* shl   = sm + O_HL;    // h_last [u][b] stride 33
    float* sWlin = sm + O_WL;
    float* sblin = sm + O_BL;

    const int n   = blockIdx.x;
    const int tid = threadIdx.x;
    const int tm  = tid >> 5;   // warp = batch group 4tm..4tm+3
    const int tn  = tid & 31;   // lane = unit pair {2tn, 2tn+1}

    const float* whh = W_hh + (size_t)n * 256 * 64;
    for (int i = tid; i < 16384; i += 256) {
        int j = i >> 6, k = i & 63;
        sWhh[k * 256 + j] = whh[i];
    }
    for (int i = tid; i < FUT * HL; i += 256) sWlin[i] = W_lin[i];
    if (tid < FUT) sblin[tid] = b_lin[tid];
    __syncthreads();   // weights visible; no more block syncs until the tail

    // h registers: h0[mi] = unit 2tn, h1[mi] = unit 2tn+1, batch 4tm+mi
    float h0[4], h1[4], c[4][2];
    #pragma unroll
    for (int mi = 0; mi < 4; mi++) {
        h0[mi] = 0.f; h1[mi] = 0.f;
        c[mi][0] = 0.f; c[mi][1] = 0.f;
    }

    const float* gptr = g_gates + (size_t)n * TT * BB * 256;

    // prefetch gates(t=0)
    float gb[4][8];
    #pragma unroll
    for (int mi = 0; mi < 4; mi++)
        #pragma unroll
        for (int gg = 0; gg < 4; gg++) {
            float2 v = *(const float2*)&gptr[(4 * tm + mi) * 256 + gg * 64 + 2 * tn];
            gb[mi][gg * 2] = v.x; gb[mi][gg * 2 + 1] = v.y;
        }

    for (int t = 0; t < TT; t++) {
        float acc[4][8];
        #pragma unroll
        for (int mi = 0; mi < 4; mi++)
            #pragma unroll
            for (int q = 0; q < 8; q++) acc[mi][q] = gb[mi][q];

        // prefetch gates(t+1) — latency hidden under k-loop
        if (t + 1 < TT) {
            const float* gnx = gptr + (size_t)(t + 1) * BB * 256;
            #pragma unroll
            for (int mi = 0; mi < 4; mi++)
                #pragma unroll
                for (int gg = 0; gg < 4; gg++) {
                    float2 v = *(const float2*)&gnx[(4 * tm + mi) * 256 + gg * 64 + 2 * tn];
                    gb[mi][gg * 2] = v.x; gb[mi][gg * 2 + 1] = v.y;
                }
        }

        // GEMM over k: h from warp registers via shfl (k&1 is compile-time
        // constant inside the even-unrolled loop)
        #pragma unroll 8
        for (int k = 0; k < 64; k++) {
            const int r = k >> 1;
            float hv[4];
            #pragma unroll
            for (int mi = 0; mi < 4; mi++)
                hv[mi] = __shfl_sync(0xffffffffu,
                                     (k & 1) ? h1[mi] : h0[mi], r);
            #pragma unroll
            for (int gg = 0; gg < 4; gg++) {
                float2 w = *(const float2*)&sWhh[k * 256 + gg * 64 + 2 * tn];
                #pragma unroll
                for (int mi = 0; mi < 4; mi++) {
                    acc[mi][gg * 2 + 0] += hv[mi] * w.x;
                    acc[mi][gg * 2 + 1] += hv[mi] * w.y;
                }
            }
        }

        // cell update (gate order i, f, g, o); writes h registers only
        #pragma unroll
        for (int mi = 0; mi < 4; mi++) {
            {
                float ig = sigm(acc[mi][0]);
                float fg = sigm(acc[mi][2]);
                float gv = tanh_fast(acc[mi][4]);
                float og = sigm(acc[mi][6]);
                float cc = fg * c[mi][0] + ig * gv;
                c[mi][0] = cc;
                h0[mi] = og * tanh_fast(cc);
            }
            {
                float ig = sigm(acc[mi][1]);
                float fg = sigm(acc[mi][3]);
                float gv = tanh_fast(acc[mi][5]);
                float og = sigm(acc[mi][7]);
                float cc = fg * c[mi][1] + ig * gv;
                c[mi][1] = cc;
                h1[mi] = og * tanh_fast(cc);
            }
        }
    }

    // stage h_last to SMEM for the head GEMM
    #pragma unroll
    for (int mi = 0; mi < 4; mi++) {
        shl[(2 * tn + 0) * 33 + (4 * tm + mi)] = h0[mi];
        shl[(2 * tn + 1) * 33 + (4 * tm + mi)] = h1[mi];
    }
    __syncthreads();

    // head: pred[b][n][f] = leaky(h_last[b] . W_lin[f] + b_lin[f])
    for (int idx = tid; idx < BB * FUT; idx += 256) {
        int b = idx / FUT;
        int f = idx % FUT;
        float acc = sblin[f];
        #pragma unroll
        for (int u = 0; u < HL; u++)
            acc += shl[u * 33 + b] * sWlin[f * HL + u];
        float v = acc > 0.f ? acc : 0.01f * acc;
        out[((size_t)b * NH + n) * FUT + f] = v;
    }
}

// ---------------------------------------------------------------------------
extern "C" void kernel_launch(void* const* d_in, const int* in_sizes, int n_in,
                              void* d_out, int out_size)
{
    const float* data_meteo = (const float*)d_in[0];
    const float* data_hydro = (const float*)d_in[1];
    const int*   eh         = (const int*)  d_in[2];
    const int*   em         = (const int*)  d_in[3];
    const float* W_rel_m    = (const float*)d_in[4];
    const float* b_rel_m    = (const float*)d_in[5];
    const float* W_root_m   = (const float*)d_in[6];
    const float* W_rel_h    = (const float*)d_in[7];
    const float* b_rel_h    = (const float*)d_in[8];
    const float* W_root_h   = (const float*)d_in[9];
    const float* W_ih       = (const float*)d_in[10];
    const float* W_hh       = (const float*)d_in[11];
    const float* b_ih       = (const float*)d_in[12];
    const float* b_hh       = (const float*)d_in[13];
    const float* W_lin      = (const float*)d_in[14];
    const float* b_lin      = (const float*)d_in[15];

    const int Eh = in_sizes[2] / 2;
    const int Em = in_sizes[3] / 2;

    csr_kernel<<<1, 256>>>(eh, em, Eh, Em);

    gnn_kernel<<<(BB * TT) / TB, 256>>>(data_meteo, data_hydro,
                                        W_rel_m, b_rel_m, W_root_m,
                                        W_rel_h, b_rel_h, W_root_h);

    cudaFuncSetAttribute(xgemm_kernel,
                         cudaFuncAttributeMaxDynamicSharedMemorySize, XG_BYTES);
    dim3 xg(NH, TT / TC);
    xgemm_kernel<<<xg, 256, XG_BYTES>>>(W_ih, b_ih, b_hh);

    cudaFuncSetAttribute(lstm_kernel,
                         cudaFuncAttributeMaxDynamicSharedMemorySize, LS_BYTES);
    lstm_kernel<<<NH, 256, LS_BYTES>>>(W_hh, W_lin, b_lin, (float*)d_out);
}

// round 12
// speedup vs baseline: 1.3524x; 1.0697x over previous
#include <cuda_runtime.h>
#include <cstdint>

#define BB   32
#define TT   336
#define NH   100
#define NM   150
#define FH   8
#define FM   16
#define HG   64
#define HL   64
#define FUT  24
#define TC   16          // timesteps per xgemm chunk (= flag granule)
#define NCK  (TT / TC)   // 21 chunks
#define TB   16          // graphs per gnn block

// GNN output x: [n][t][b][hg]
__device__ float g_x[(size_t)NH * TT * BB * HG];
// Precomputed x-gates (+bias): [n][t][b][256]
__device__ float g_gates[(size_t)NH * TT * BB * 256];
// producer->consumer readiness flags, one per (node, chunk)
__device__ int d_flag[NH * NCK];

// CSR edge structure (built once per launch, deterministic order)
__device__ int d_off_h[NH], d_deg_h[NH], d_src_h[512];
__device__ int d_off_m[NH], d_deg_m[NH], d_src_m[1024];

// ---------------------------------------------------------------------------
// Kernel A0: build CSR by target node; also zero the handshake flags.
// ---------------------------------------------------------------------------
__global__ void __launch_bounds__(256) csr_kernel(
    const int* __restrict__ eh, const int* __restrict__ em, int Eh, int Em)
{
    __shared__ int s_src[1024], s_tgt[1024];
    const int tid = threadIdx.x;

    for (int i = tid; i < NH * NCK; i += 256) d_flag[i] = 0;

    for (int i = tid; i < Eh; i += 256) { s_src[i] = eh[i]; s_tgt[i] = eh[Eh + i]; }
    __syncthreads();
    if (tid < NH) {
        int start = 0;
        for (int e = 0; e < Eh; e++) start += (s_tgt[e] < tid) ? 1 : 0;
        int p = start, cnt = 0;
        for (int e = 0; e < Eh; e++)
            if (s_tgt[e] == tid) { d_src_h[p++] = s_src[e]; cnt++; }
        d_off_h[tid] = start; d_deg_h[tid] = cnt;
    }
    __syncthreads();
    for (int i = tid; i < Em; i += 256) { s_src[i] = em[i]; s_tgt[i] = em[Em + i]; }
    __syncthreads();
    if (tid < NH) {
        int start = 0;
        for (int e = 0; e < Em; e++) start += (s_tgt[e] < tid) ? 1 : 0;
        int p = start, cnt = 0;
        for (int e = 0; e < Em; e++)
            if (s_tgt[e] == tid) { d_src_m[p++] = s_src[e]; cnt++; }
        d_off_m[tid] = start; d_deg_m[tid] = cnt;
    }
}

// ---------------------------------------------------------------------------
// Kernel A: hetero GraphConv, TB graphs per block, CSR gather. (R6, verified)
// ---------------------------------------------------------------------------
__global__ void __launch_bounds__(256) gnn_kernel(
    const float* __restrict__ xm_all, const float* __restrict__ xh_all,
    const float* __restrict__ Wrel_m, const float* __restrict__ brel_m,
    const float* __restrict__ Wroot_m,
    const float* __restrict__ Wrel_h, const float* __restrict__ brel_h,
    const float* __restrict__ Wroot_h)
{
    __shared__ float swh[FH * HG];
    __shared__ float swr[FH * HG];
    __shared__ float swm[FM * HG];
    __shared__ float sb[HG];
    __shared__ int soff_h[NH], sdeg_h[NH], ssrc_h[512];
    __shared__ int soff_m[NH], sdeg_m[NH], ssrc_m[1024];
    __shared__ float sxh[NH * FH];
    __shared__ float sxm[NM * FM];
    __shared__ float sah[NH * FH];
    __shared__ float sam[NH * FM];

    const int tid = threadIdx.x;

    for (int i = tid; i < HG * FH; i += 256) {
        int j = i / FH, k = i % FH;
        swh[k * HG + j] = 0.5f * Wrel_h[i];
        swr[k * HG + j] = 0.5f * (Wroot_h[i] + Wroot_m[i]);
    }
    for (int i = tid; i < HG * FM; i += 256) {
        int j = i / FM, k = i % FM;
        swm[k * HG + j] = 0.5f * Wrel_m[i];
    }
    for (int i = tid; i < HG; i += 256) sb[i] = 0.5f * (brel_h[i] + brel_m[i]);
    for (int i = tid; i < NH; i += 256) {
        soff_h[i] = d_off_h[i]; sdeg_h[i] = d_deg_h[i];
        soff_m[i] = d_off_m[i]; sdeg_m[i] = d_deg_m[i];
    }
    for (int i = tid; i < 512;  i += 256) ssrc_h[i] = d_src_h[i];
    for (int i = tid; i < 1024; i += 256) ssrc_m[i] = d_src_m[i];

    for (int gi = 0; gi < TB; gi++) {
        const int g = blockIdx.x * TB + gi;
        const float* xh = xh_all + (size_t)g * NH * FH;
        const float* xm = xm_all + (size_t)g * NM * FM;

        __syncthreads();
        for (int i = tid; i < NH * FH / 4; i += 256)
            *(float4*)&sxh[i * 4] = *(const float4*)&xh[i * 4];
        for (int i = tid; i < NM * FM / 4; i += 256)
            *(float4*)&sxm[i * 4] = *(const float4*)&xm[i * 4];
        __syncthreads();

        for (int idx = tid; idx < NH * FH; idx += 256) {
            int n = idx >> 3, k = idx & 7;
            int o = soff_h[n], d = sdeg_h[n];
            float s = 0.f;
            for (int e = 0; e < d; e++) s += sxh[ssrc_h[o + e] * FH + k];
            sah[idx] = s;
        }
        for (int idx = tid; idx < NH * FM; idx += 256) {
            int n = idx >> 4, k = idx & 15;
            int o = soff_m[n], d = sdeg_m[n];
            float s = 0.f;
            for (int e = 0; e < d; e++) s += sxm[ssrc_m[o + e] * FM + k];
            sam[idx] = s;
        }
        __syncthreads();

        const int t = g % TT;
        const int b = g / TT;
        for (int idx = tid; idx < NH * HG; idx += 256) {
            int n = idx >> 6, j = idx & 63;
            float acc = sb[j];
            #pragma unroll
            for (int k = 0; k < FH; k++)
                acc += sah[n * FH + k] * swh[k * HG + j]
                     + sxh[n * FH + k] * swr[k * HG + j];
            #pragma unroll
            for (int k = 0; k < FM; k++)
                acc += sam[n * FM + k] * swm[k * HG + j];
            float v = acc > 0.f ? acc : 0.01f * acc;
            g_x[(((size_t)n * TT + t) * BB + b) * HG + j] = v;
        }
    }
}

// ---------------------------------------------------------------------------
// FUSED kernel: blockIdx < NH  -> LSTM consumer role (warp-local recurrence)
//               blockIdx >= NH -> xgemm producer role (one (node,chunk) each,
//                                 chunk-major order so chunk 0 lands first)
// Producer publishes d_flag[n][ck] after fence; consumer acquire-polls.
// No deadlock: 100 consumer blocks can never fill all 148 SMs, so producer
// blocks are always schedulable and make independent forward progress.
// ---------------------------------------------------------------------------
#define O_WHH 0
#define O_HL  16384               // h_last staging [u][b] stride 33: 2112
#define O_WL  (O_HL + 64*33)      // 24*64
#define O_BL  (O_WL + 24*64)
#define LS_FLOATS (O_BL + 32)     // 20064
#define XG_SW 0
#define XG_SB 16384
#define XG_SX (16384 + 256)
#define XG_FLOATS (XG_SX + 64*33) // 18752
#define FUSED_FLOATS (LS_FLOATS > XG_FLOATS ? LS_FLOATS : XG_FLOATS)
#define FUSED_BYTES  (FUSED_FLOATS * 4)

__device__ __forceinline__ float sigm(float x) {
    return 1.0f / (1.0f + __expf(-x));
}
__device__ __forceinline__ float tanh_fast(float x) {
    float xc = fminf(fmaxf(x, -15.f), 15.f);
    float e = __expf(2.0f * xc);
    return (e - 1.0f) / (e + 1.0f);
}
__device__ __forceinline__ void wait_flag(const int* f) {
    int v;
    for (;;) {
        asm volatile("ld.acquire.gpu.s32 %0, [%1];" : "=r"(v) : "l"(f) : "memory");
        if (v) break;
        __nanosleep(200);
    }
}

__global__ void __launch_bounds__(256) fused_kernel(
    const float* __restrict__ W_ih, const float* __restrict__ W_hh,
    const float* __restrict__ b_ih, const float* __restrict__ b_hh,
    const float* __restrict__ W_lin, const float* __restrict__ b_lin,
    float* __restrict__ out)
{
    extern __shared__ float sm[];
    const int tid = threadIdx.x;

    if (blockIdx.x >= NH) {
        // ----------------- producer role: xgemm for (n, ck) -----------------
        const int id = blockIdx.x - NH;
        const int ck = id / NH;          // chunk-major: all nodes' ck=0 first
        const int n  = id % NH;
        const int t0 = ck * TC;

        float* sW = sm + XG_SW;
        float* sb = sm + XG_SB;
        float* sx = sm + XG_SX;

        const float* w = W_ih + (size_t)n * 256 * 64;
        for (int i = tid; i < 16384; i += 256) {
            int j = i >> 6, k = i & 63;
            sW[k * 256 + j] = w[i];
        }
        sb[tid] = b_ih[n * 256 + tid] + b_hh[n * 256 + tid];

        const int tm = tid >> 5;
        const int tn = tid & 31;
        const int sb_b = tid >> 3;
        const int sb_k = (tid & 7) << 3;

        const float* xbase = g_x + ((size_t)n * TT + t0) * BB * HG;
        float* gbase = g_gates + ((size_t)n * TT + t0) * BB * 256;
        __syncthreads();

        for (int tt = 0; tt < TC; tt++) {
            const float* xt = xbase + (size_t)tt * BB * HG;
            float4 v0 = *(const float4*)&xt[sb_b * HG + sb_k];
            float4 v1 = *(const float4*)&xt[sb_b * HG + sb_k + 4];
            sx[(sb_k + 0) * 33 + sb_b] = v0.x;
            sx[(sb_k + 1) * 33 + sb_b] = v0.y;
            sx[(sb_k + 2) * 33 + sb_b] = v0.z;
            sx[(sb_k + 3) * 33 + sb_b] = v0.w;
            sx[(sb_k + 4) * 33 + sb_b] = v1.x;
            sx[(sb_k + 5) * 33 + sb_b] = v1.y;
            sx[(sb_k + 6) * 33 + sb_b] = v1.z;
            sx[(sb_k + 7) * 33 + sb_b] = v1.w;
            __syncthreads();

            float acc[4][8];
            #pragma unroll
            for (int mi = 0; mi < 4; mi++)
                #pragma unroll
                for (int gg = 0; gg < 4; gg++) {
                    acc[mi][gg * 2 + 0] = sb[gg * 64 + 2 * tn + 0];
                    acc[mi][gg * 2 + 1] = sb[gg * 64 + 2 * tn + 1];
                }

            #pragma unroll 4
            for (int k = 0; k < 64; k++) {
                float xv[4];
                #pragma unroll
                for (int mi = 0; mi < 4; mi++) xv[mi] = sx[k * 33 + 4 * tm + mi];
                #pragma unroll
                for (int gg = 0; gg < 4; gg++) {
                    float2 wv = *(const float2*)&sW[k * 256 + gg * 64 + 2 * tn];
                    #pragma unroll
                    for (int mi = 0; mi < 4; mi++) {
                        acc[mi][gg * 2 + 0] += xv[mi] * wv.x;
                        acc[mi][gg * 2 + 1] += xv[mi] * wv.y;
                    }
                }
            }

            float* gt = gbase + (size_t)tt * BB * 256;
            #pragma unroll
            for (int mi = 0; mi < 4; mi++)
                #pragma unroll
                for (int gg = 0; gg < 4; gg++) {
                    float2 v; v.x = acc[mi][gg * 2]; v.y = acc[mi][gg * 2 + 1];
                    *(float2*)&gt[(4 * tm + mi) * 256 + gg * 64 + 2 * tn] = v;
                }
            __syncthreads();
        }

        __syncthreads();
        if (tid == 0) {
            __threadfence();
            atomicExch(&d_flag[n * NCK + ck], 1);
        }
        return;
    }

    // ------------------- consumer role: LSTM for node n ---------------------
    const int n  = blockIdx.x;
    const int tm = tid >> 5;   // warp = batch group 4tm..4tm+3
    const int tn = tid & 31;   // lane = unit pair {2tn, 2tn+1}

    float* sWhh  = sm + O_WHH;   // [k][j] stride 256
    float* shl   = sm + O_HL;    // h_last [u][b] stride 33
    float* sWlin = sm + O_WL;
    float* sblin = sm + O_BL;

    const float* whh = W_hh + (size_t)n * 256 * 64;
    for (int i = tid; i < 16384; i += 256) {
        int j = i >> 6, k = i & 63;
        sWhh[k * 256 + j] = whh[i];
    }
    for (int i = tid; i < FUT * HL; i += 256) sWlin[i] = W_lin[i];
    if (tid < FUT) sblin[tid] = b_lin[tid];
    __syncthreads();   // weights visible; no more block syncs until the tail

    const int* flg = &d_flag[n * NCK];

    float h0[4], h1[4], c[4][2];
    #pragma unroll
    for (int mi = 0; mi < 4; mi++) {
        h0[mi] = 0.f; h1[mi] = 0.f;
        c[mi][0] = 0.f; c[mi][1] = 0.f;
    }

    const float* gptr = g_gates + (size_t)n * TT * BB * 256;

    // wait for chunk 0, then prefetch gates(t=0)
    wait_flag(&flg[0]);
    float gb[4][8];
    #pragma unroll
    for (int mi = 0; mi < 4; mi++)
        #pragma unroll
        for (int gg = 0; gg < 4; gg++) {
            float2 v = *(const float2*)&gptr[(4 * tm + mi) * 256 + gg * 64 + 2 * tn];
            gb[mi][gg * 2] = v.x; gb[mi][gg * 2 + 1] = v.y;
        }

    for (int t = 0; t < TT; t++) {
        float acc[4][8];
        #pragma unroll
        for (int mi = 0; mi < 4; mi++)
            #pragma unroll
            for (int q = 0; q < 8; q++) acc[mi][q] = gb[mi][q];

        // prefetch gates(t+1); poll flag at chunk boundaries
        if (t + 1 < TT) {
            if (((t + 1) & (TC - 1)) == 0)
                wait_flag(&flg[(t + 1) >> 4]);
            const float* gnx = gptr + (size_t)(t + 1) * BB * 256;
            #pragma unroll
            for (int mi = 0; mi < 4; mi++)
                #pragma unroll
                for (int gg = 0; gg < 4; gg++) {
                    float2 v = *(const float2*)&gnx[(4 * tm + mi) * 256 + gg * 64 + 2 * tn];
                    gb[mi][gg * 2] = v.x; gb[mi][gg * 2 + 1] = v.y;
                }
        }

        // GEMM over k: h from warp registers via shfl
        #pragma unroll 8
        for (int k = 0; k < 64; k++) {
            const int r = k >> 1;
            float hv[4];
            #pragma unroll
            for (int mi = 0; mi < 4; mi++)
                hv[mi] = __shfl_sync(0xffffffffu,
                                     (k & 1) ? h1[mi] : h0[mi], r);
            #pragma unroll
            for (int gg = 0; gg < 4; gg++) {
                float2 w = *(const float2*)&sWhh[k * 256 + gg * 64 + 2 * tn];
                #pragma unroll
                for (int mi = 0; mi < 4; mi++) {
                    acc[mi][gg * 2 + 0] += hv[mi] * w.x;
                    acc[mi][gg * 2 + 1] += hv[mi] * w.y;
                }
            }
        }

        // cell update (gate order i, f, g, o)
        #pragma unroll
        for (int mi = 0; mi < 4; mi++) {
            {
                float ig = sigm(acc[mi][0]);
                float fg = sigm(acc[mi][2]);
                float gv = tanh_fast(acc[mi][4]);
                float og = sigm(acc[mi][6]);
                float cc = fg * c[mi][0] + ig * gv;
                c[mi][0] = cc;
                h0[mi] = og * tanh_fast(cc);
            }
            {
                float ig = sigm(acc[mi][1]);
                float fg = sigm(acc[mi][3]);
                float gv = tanh_fast(acc[mi][5]);
                float og = sigm(acc[mi][7]);
                float cc = fg * c[mi][1] + ig * gv;
                c[mi][1] = cc;
                h1[mi] = og * tanh_fast(cc);
            }
        }
    }

    // stage h_last to SMEM for the head GEMM
    #pragma unroll
    for (int mi = 0; mi < 4; mi++) {
        shl[(2 * tn + 0) * 33 + (4 * tm + mi)] = h0[mi];
        shl[(2 * tn + 1) * 33 + (4 * tm + mi)] = h1[mi];
    }
    __syncthreads();

    // head: pred[b][n][f] = leaky(h_last[b] . W_lin[f] + b_lin[f])
    for (int idx = tid; idx < BB * FUT; idx += 256) {
        int b = idx / FUT;
        int f = idx % FUT;
        float acc = sblin[f];
        #pragma unroll
        for (int u = 0; u < HL; u++)
            acc += shl[u * 33 + b] * sWlin[f * HL + u];
        float v = acc > 0.f ? acc : 0.01f * acc;
        out[((size_t)b * NH + n) * FUT + f] = v;
    }
}

// ---------------------------------------------------------------------------
extern "C" void kernel_launch(void* const* d_in, const int* in_sizes, int n_in,
                              void* d_out, int out_size)
{
    const float* data_meteo = (const float*)d_in[0];
    const float* data_hydro = (const float*)d_in[1];
    const int*   eh         = (const int*)  d_in[2];
    const int*   em         = (const int*)  d_in[3];
    const float* W_rel_m    = (const float*)d_in[4];
    const float* b_rel_m    = (const float*)d_in[5];
    const float* W_root_m   = (const float*)d_in[6];
    const float* W_rel_h    = (const float*)d_in[7];
    const float* b_rel_h    = (const float*)d_in[8];
    const float* W_root_h   = (const float*)d_in[9];
    const float* W_ih       = (const float*)d_in[10];
    const float* W_hh       = (const float*)d_in[11];
    const float* b_ih       = (const float*)d_in[12];
    const float* b_hh       = (const float*)d_in[13];
    const float* W_lin      = (const float*)d_in[14];
    const float* b_lin      = (const float*)d_in[15];

    const int Eh = in_sizes[2] / 2;
    const int Em = in_sizes[3] / 2;

    csr_kernel<<<1, 256>>>(eh, em, Eh, Em);

    gnn_kernel<<<(BB * TT) / TB, 256>>>(data_meteo, data_hydro,
                                        W_rel_m, b_rel_m, W_root_m,
                                        W_rel_h, b_rel_h, W_root_h);

    cudaFuncSetAttribute(fused_kernel,
                         cudaFuncAttributeMaxDynamicSharedMemorySize,
                         FUSED_BYTES);
    fused_kernel<<<NH + NH * NCK, 256, FUSED_BYTES>>>(
        W_ih, W_hh, b_ih, b_hh, W_lin, b_lin, (float*)d_out);
}